// round 4
// baseline (speedup 1.0000x reference)
#include <cuda_runtime.h>

// Problem: B=8, S=512, D=768, R=128
//   p_dist  = E @ Wd^T  (B,S,R)
//   p_depth = E @ Wz^T  (B,S,R)
//   distances[b,i,j] = ||p_dist[b,i]-p_dist[b,j]||^2
//                    = nd[i] + nd[j] - 2 * <p_dist[b,i], p_dist[b,j]>
//   depths[b,s]      = ||p_depth[b,s]||^2
//
// Output layout: distances (B*S*S floats) followed by depths (B*S floats).

static constexpr int Bn = 8;
static constexpr int Sn = 512;
static constexpr int Dn = 768;
static constexpr int Rn = 128;
static constexpr int Mtot = Bn * Sn;   // 4096
static constexpr int Ncat = 2 * Rn;    // 256 (cols 0..127 = dist proj, 128..255 = depth proj)

// Scratch (no cudaMalloc allowed): projected embeddings + dist-row norms
__device__ float g_P[Mtot * Ncat];     // 4 MB
__device__ float g_nd[Mtot];

// ---------------------------------------------------------------------------
// GEMM1: P[m, n] = sum_k E[m, k] * W[n, k]      (A @ B^T form)
// Tiles: BM=64, BN=64, BK=16; 256 threads; 4x4 microtile per thread.
// Shared tiles stored k-major -> conflict-free LDS.128 in the compute loop.
// ---------------------------------------------------------------------------
__global__ __launch_bounds__(256) void gemm1_kernel(const float* __restrict__ E,
                                                    const float* __restrict__ Wd,
                                                    const float* __restrict__ Wz) {
    __shared__ float As[16][64];
    __shared__ float Bs[16][64];

    const int tid = threadIdx.x;
    const int tx = tid & 15;          // 0..15 -> n microtile
    const int ty = tid >> 4;          // 0..15 -> m microtile
    const int m0 = blockIdx.y * 64;
    const int nt = blockIdx.x;        // 0..3 (n tile of 64)

    // Select which projection matrix this n-tile comes from (uniform per block)
    const float* __restrict__ Bmat =
        (nt < 2) ? (Wd + (size_t)nt * 64 * Dn)
                 : (Wz + (size_t)(nt - 2) * 64 * Dn);

    const int lr = tid >> 2;          // 0..63  (tile row to load)
    const int lk = (tid & 3) * 4;     // 0,4,8,12 (k offset, float4)

    float c[4][4];
#pragma unroll
    for (int i = 0; i < 4; i++)
#pragma unroll
        for (int j = 0; j < 4; j++) c[i][j] = 0.0f;

    const float* aptr = E + (size_t)(m0 + lr) * Dn + lk;
    const float* bptr = Bmat + (size_t)lr * Dn + lk;

    for (int k0 = 0; k0 < Dn; k0 += 16) {
        float4 av = *(const float4*)(aptr + k0);
        float4 bv = *(const float4*)(bptr + k0);
        As[lk + 0][lr] = av.x; As[lk + 1][lr] = av.y;
        As[lk + 2][lr] = av.z; As[lk + 3][lr] = av.w;
        Bs[lk + 0][lr] = bv.x; Bs[lk + 1][lr] = bv.y;
        Bs[lk + 2][lr] = bv.z; Bs[lk + 3][lr] = bv.w;
        __syncthreads();

#pragma unroll
        for (int kk = 0; kk < 16; kk++) {
            float4 a = *(const float4*)&As[kk][ty * 4];
            float4 b = *(const float4*)&Bs[kk][tx * 4];
            c[0][0] += a.x * b.x; c[0][1] += a.x * b.y; c[0][2] += a.x * b.z; c[0][3] += a.x * b.w;
            c[1][0] += a.y * b.x; c[1][1] += a.y * b.y; c[1][2] += a.y * b.z; c[1][3] += a.y * b.w;
            c[2][0] += a.z * b.x; c[2][1] += a.z * b.y; c[2][2] += a.z * b.z; c[2][3] += a.z * b.w;
            c[3][0] += a.w * b.x; c[3][1] += a.w * b.y; c[3][2] += a.w * b.z; c[3][3] += a.w * b.w;
        }
        __syncthreads();
    }

    const int n0 = nt * 64 + tx * 4;
#pragma unroll
    for (int i = 0; i < 4; i++) {
        float4 v = make_float4(c[i][0], c[i][1], c[i][2], c[i][3]);
        *(float4*)&g_P[(size_t)(m0 + ty * 4 + i) * Ncat + n0] = v;
    }
}

// ---------------------------------------------------------------------------
// Norms: nd[m] = ||P[m, 0:128]||^2 (scratch), depths[m] = ||P[m,128:256]||^2 (output)
// One warp per row; 8 warps per block.
// ---------------------------------------------------------------------------
__global__ __launch_bounds__(256) void norms_kernel(float* __restrict__ out_depths) {
    const int row = blockIdx.x * 8 + (threadIdx.x >> 5);
    const int lane = threadIdx.x & 31;

    const float4* p4 = (const float4*)(g_P + (size_t)row * Ncat);
    float4 a = p4[lane];        // floats 0..127   (dist projection)
    float4 d = p4[32 + lane];   // floats 128..255 (depth projection)

    float nd = a.x * a.x + a.y * a.y + a.z * a.z + a.w * a.w;
    float dp = d.x * d.x + d.y * d.y + d.z * d.z + d.w * d.w;

#pragma unroll
    for (int off = 16; off > 0; off >>= 1) {
        nd += __shfl_xor_sync(0xffffffffu, nd, off);
        dp += __shfl_xor_sync(0xffffffffu, dp, off);
    }
    if (lane == 0) {
        g_nd[row] = nd;
        out_depths[row] = dp;
    }
}

// ---------------------------------------------------------------------------
// GEMM2 (per batch): G = P_b @ P_b^T over K=128 (dist cols), epilogue
//   out[b,i,j] = nd[i] + nd[j] - 2*G[i,j]
// Tiles: BM=BN=64, BK=16; 256 threads; 4x4 microtile.
// ---------------------------------------------------------------------------
__global__ __launch_bounds__(256) void gemm2_kernel(float* __restrict__ out) {
    __shared__ float As[16][64];
    __shared__ float Bs[16][64];

    const int tid = threadIdx.x;
    const int tx = tid & 15;
    const int ty = tid >> 4;
    const int b  = blockIdx.z;
    const int m0 = blockIdx.y * 64;
    const int n0 = blockIdx.x * 64;

    const float* __restrict__ P = g_P + (size_t)b * Sn * Ncat;

    const int lr = tid >> 2;
    const int lk = (tid & 3) * 4;

    float c[4][4];
#pragma unroll
    for (int i = 0; i < 4; i++)
#pragma unroll
        for (int j = 0; j < 4; j++) c[i][j] = 0.0f;

    const float* aptr = P + (size_t)(m0 + lr) * Ncat + lk;
    const float* bptr = P + (size_t)(n0 + lr) * Ncat + lk;

    for (int k0 = 0; k0 < Rn; k0 += 16) {
        float4 av = *(const float4*)(aptr + k0);
        float4 bv = *(const float4*)(bptr + k0);
        As[lk + 0][lr] = av.x; As[lk + 1][lr] = av.y;
        As[lk + 2][lr] = av.z; As[lk + 3][lr] = av.w;
        Bs[lk + 0][lr] = bv.x; Bs[lk + 1][lr] = bv.y;
        Bs[lk + 2][lr] = bv.z; Bs[lk + 3][lr] = bv.w;
        __syncthreads();

#pragma unroll
        for (int kk = 0; kk < 16; kk++) {
            float4 a = *(const float4*)&As[kk][ty * 4];
            float4 b2 = *(const float4*)&Bs[kk][tx * 4];
            c[0][0] += a.x * b2.x; c[0][1] += a.x * b2.y; c[0][2] += a.x * b2.z; c[0][3] += a.x * b2.w;
            c[1][0] += a.y * b2.x; c[1][1] += a.y * b2.y; c[1][2] += a.y * b2.z; c[1][3] += a.y * b2.w;
            c[2][0] += a.z * b2.x; c[2][1] += a.z * b2.y; c[2][2] += a.z * b2.z; c[2][3] += a.z * b2.w;
            c[3][0] += a.w * b2.x; c[3][1] += a.w * b2.y; c[3][2] += a.w * b2.z; c[3][3] += a.w * b2.w;
        }
        __syncthreads();
    }

    const float* __restrict__ ndp = g_nd + (size_t)b * Sn;
    float ndi[4], ndj[4];
#pragma unroll
    for (int i = 0; i < 4; i++) ndi[i] = ndp[m0 + ty * 4 + i];
#pragma unroll
    for (int j = 0; j < 4; j++) ndj[j] = ndp[n0 + tx * 4 + j];

    float* obase = out + ((size_t)b * Sn) * Sn;
#pragma unroll
    for (int i = 0; i < 4; i++) {
        const int mi = m0 + ty * 4 + i;
        float4 v;
        v.x = ndi[i] + ndj[0] - 2.0f * c[i][0];
        v.y = ndi[i] + ndj[1] - 2.0f * c[i][1];
        v.z = ndi[i] + ndj[2] - 2.0f * c[i][2];
        v.w = ndi[i] + ndj[3] - 2.0f * c[i][3];
        *(float4*)&obase[(size_t)mi * Sn + n0 + tx * 4] = v;
    }
}

// ---------------------------------------------------------------------------
extern "C" void kernel_launch(void* const* d_in, const int* in_sizes, int n_in,
                              void* d_out, int out_size) {
    const float* E  = (const float*)d_in[0];   // embeddings (B,S,D)
    const float* Wd = (const float*)d_in[1];   // proj_dist  (R,D)
    const float* Wz = (const float*)d_in[2];   // proj_depth (R,D)
    float* out = (float*)d_out;

    // Stage A: fused projection GEMM -> g_P
    gemm1_kernel<<<dim3(4, Mtot / 64), 256>>>(E, Wd, Wz);
    // Stage B: row norms -> g_nd (dist) and depths output
    norms_kernel<<<Mtot / 8, 256>>>(out + (size_t)Bn * Sn * Sn);
    // Stage C: per-batch gram + distance epilogue -> distances output
    gemm2_kernel<<<dim3(Sn / 64, Sn / 64, Bn), 256>>>(out);
}

// round 7
// speedup vs baseline: 1.6288x; 1.6288x over previous
#include <cuda_runtime.h>
#include <cuda_bf16.h>
#include <mma.h>
#include <cstdint>

using namespace nvcuda;

// Problem: B=8, S=512, D=768, R=128
//   P = E @ [Wd;Wz]^T ; distances[b,i,j] = nd_i + nd_j - 2<Pd_i,Pd_j>; depths = ||Pz||^2
// Strategy: WMMA bf16 (m16n16k16, fp32 accum) with 3-term hi/lo split (~fp32 precision).
// NOTE: tcgen05 is unusable here — harness PTX target is plain sm_103 (no 'a'),
// so only baseline-ISA tensor ops (mma.sync/HMMA) are available.
// Output: distances (B*S*S floats) then depths (B*S floats).

static constexpr int Bn = 8;
static constexpr int Sn = 512;
static constexpr int Dn = 768;
static constexpr int Mtot = Bn * Sn;   // 4096
static constexpr int Ncat = 256;       // cols 0..127 dist, 128..255 depth

static constexpr int AP = 72;          // padded lda for bf16 smem tiles (64+8)
static constexpr int SMEM_G = (128 * AP + 128 * AP + 64 * AP + 64 * AP) * 2; // 55296 B

// Scratch (no cudaMalloc allowed)
__device__ __align__(256) float g_P[Mtot * Ncat];             // 4 MB fp32 projections
__device__ __align__(256) __nv_bfloat16 g_Phi[Mtot * 128];    // dist proj hi
__device__ __align__(256) __nv_bfloat16 g_Plo[Mtot * 128];    // dist proj lo
__device__ float g_nd[Mtot];

__device__ __forceinline__ uint32_t smem_u32(const void* p) {
    return (uint32_t)__cvta_generic_to_shared(p);
}
__device__ __forceinline__ void sts128(uint32_t a, uint32_t x, uint32_t y, uint32_t z, uint32_t w) {
    asm volatile("st.shared.v4.b32 [%0], {%1,%2,%3,%4};"
                 :: "r"(a), "r"(x), "r"(y), "r"(z), "r"(w) : "memory");
}
// split fp32 pair -> packed bf16 hi pair + packed bf16 lo (residual) pair
__device__ __forceinline__ void split2(float a, float b, uint32_t& h2, uint32_t& l2) {
    __nv_bfloat16 ha = __float2bfloat16(a), hb = __float2bfloat16(b);
    float ra = a - __bfloat162float(ha);
    float rb = b - __bfloat162float(hb);
    __nv_bfloat16 la = __float2bfloat16(ra), lb = __float2bfloat16(rb);
    h2 = (uint32_t)__bfloat16_as_ushort(ha) | ((uint32_t)__bfloat16_as_ushort(hb) << 16);
    l2 = (uint32_t)__bfloat16_as_ushort(la) | ((uint32_t)__bfloat16_as_ushort(lb) << 16);
}

typedef wmma::fragment<wmma::matrix_a, 16, 16, 16, __nv_bfloat16, wmma::row_major> FragA;
typedef wmma::fragment<wmma::matrix_b, 16, 16, 16, __nv_bfloat16, wmma::col_major> FragB;
typedef wmma::fragment<wmma::accumulator, 16, 16, 16, float> FragC;

// ---------------------------------------------------------------------------
// GEMM1: P = E @ W^T.  BM=128, BN=64, BK=64, 256 thr (8 warps, 4x2, 32x32/warp).
// Register-prefetch pipelined over 12 K-chunks; fp32 -> bf16 hi/lo split at STS.
// grid = (4 ntiles of 64, 32 mtiles of 128)
// ---------------------------------------------------------------------------
__global__ __launch_bounds__(256, 1) void gemm1_wmma(const float* __restrict__ E,
                                                     const float* __restrict__ Wd,
                                                     const float* __restrict__ Wz) {
    extern __shared__ __align__(16) char sm[];
    __nv_bfloat16* Ahi = (__nv_bfloat16*)sm;       // [128][AP]
    __nv_bfloat16* Alo = Ahi + 128 * AP;
    __nv_bfloat16* Bhi = Alo + 128 * AP;           // [64][AP]
    __nv_bfloat16* Blo = Bhi + 64 * AP;

    const int tid = threadIdx.x;
    const int wid = tid >> 5;
    const int wm = wid >> 1, wn = wid & 1;         // warp grid 4x2
    const int m0 = blockIdx.y * 128;
    const int nt = blockIdx.x;
    const float* __restrict__ Bsrc =
        (nt < 2) ? (Wd + (size_t)nt * 64 * Dn) : (Wz + (size_t)(nt - 2) * 64 * Dn);

    FragC acc[2][2];
#pragma unroll
    for (int i = 0; i < 2; i++)
#pragma unroll
        for (int j = 0; j < 2; j++) wmma::fill_fragment(acc[i][j], 0.0f);

    const int arow = tid >> 1, acol = (tid & 1) * 32;   // A: 2 thr/row, 32 cols each
    const int brow = tid >> 2, bcol = (tid & 3) * 16;   // B: 4 thr/row, 16 cols each
    const float* __restrict__ ag = E + (size_t)(m0 + arow) * Dn + acol;
    const float* __restrict__ bg = Bsrc + (size_t)brow * Dn + bcol;

    float4 ra[8], rb[4];
#pragma unroll
    for (int q = 0; q < 8; q++) ra[q] = *(const float4*)(ag + q * 4);
#pragma unroll
    for (int q = 0; q < 4; q++) rb[q] = *(const float4*)(bg + q * 4);

    const uint32_t sAhi = smem_u32(Ahi) + (uint32_t)(arow * AP + acol) * 2;
    const uint32_t sAlo = smem_u32(Alo) + (uint32_t)(arow * AP + acol) * 2;
    const uint32_t sBhi = smem_u32(Bhi) + (uint32_t)(brow * AP + bcol) * 2;
    const uint32_t sBlo = smem_u32(Blo) + (uint32_t)(brow * AP + bcol) * 2;

    for (int c = 0; c < 12; c++) {
        // STS current chunk (split fp32 -> bf16 hi/lo)
#pragma unroll
        for (int q = 0; q < 4; q++) {
            uint32_t h0, l0, h1, l1, h2, l2, h3, l3;
            split2(ra[2 * q].x, ra[2 * q].y, h0, l0);
            split2(ra[2 * q].z, ra[2 * q].w, h1, l1);
            split2(ra[2 * q + 1].x, ra[2 * q + 1].y, h2, l2);
            split2(ra[2 * q + 1].z, ra[2 * q + 1].w, h3, l3);
            sts128(sAhi + q * 16, h0, h1, h2, h3);
            sts128(sAlo + q * 16, l0, l1, l2, l3);
        }
#pragma unroll
        for (int q = 0; q < 2; q++) {
            uint32_t h0, l0, h1, l1, h2, l2, h3, l3;
            split2(rb[2 * q].x, rb[2 * q].y, h0, l0);
            split2(rb[2 * q].z, rb[2 * q].w, h1, l1);
            split2(rb[2 * q + 1].x, rb[2 * q + 1].y, h2, l2);
            split2(rb[2 * q + 1].z, rb[2 * q + 1].w, h3, l3);
            sts128(sBhi + q * 16, h0, h1, h2, h3);
            sts128(sBlo + q * 16, l0, l1, l2, l3);
        }
        __syncthreads();

        // Prefetch next chunk (LDG latency overlaps MMA below)
        if (c < 11) {
            const float* ap = ag + (c + 1) * 64;
            const float* bp = bg + (c + 1) * 64;
#pragma unroll
            for (int q = 0; q < 8; q++) ra[q] = *(const float4*)(ap + q * 4);
#pragma unroll
            for (int q = 0; q < 4; q++) rb[q] = *(const float4*)(bp + q * 4);
        }

#pragma unroll
        for (int kk = 0; kk < 64; kk += 16) {
            FragA ah[2], al[2];
            FragB bh[2], bl[2];
#pragma unroll
            for (int f = 0; f < 2; f++) {
                const int r = wm * 32 + f * 16;
                wmma::load_matrix_sync(ah[f], Ahi + r * AP + kk, AP);
                wmma::load_matrix_sync(al[f], Alo + r * AP + kk, AP);
                const int n = wn * 32 + f * 16;
                wmma::load_matrix_sync(bh[f], Bhi + n * AP + kk, AP);
                wmma::load_matrix_sync(bl[f], Blo + n * AP + kk, AP);
            }
#pragma unroll
            for (int i = 0; i < 2; i++)
#pragma unroll
                for (int j = 0; j < 2; j++) {
                    wmma::mma_sync(acc[i][j], ah[i], bh[j], acc[i][j]);
                    wmma::mma_sync(acc[i][j], ah[i], bl[j], acc[i][j]);
                    wmma::mma_sync(acc[i][j], al[i], bh[j], acc[i][j]);
                }
        }
        __syncthreads();
    }

    float* outp = g_P + (size_t)(m0 + wm * 32) * Ncat + nt * 64 + wn * 32;
#pragma unroll
    for (int i = 0; i < 2; i++)
#pragma unroll
        for (int j = 0; j < 2; j++)
            wmma::store_matrix_sync(outp + (size_t)i * 16 * Ncat + j * 16, acc[i][j],
                                    Ncat, wmma::mem_row_major);
}

// ---------------------------------------------------------------------------
// Norms: nd = ||P[:,0:128]||^2, depths = ||P[:,128:256]||^2; also emit bf16
// hi/lo of the dist projection for GEMM2. One warp per row.
// ---------------------------------------------------------------------------
__global__ __launch_bounds__(256) void norms_kernel(float* __restrict__ out_depths) {
    const int row = blockIdx.x * 8 + (threadIdx.x >> 5);
    const int lane = threadIdx.x & 31;

    const float4* p4 = (const float4*)(g_P + (size_t)row * Ncat);
    float4 a = p4[lane];        // dist cols 4*lane..4*lane+3
    float4 d = p4[32 + lane];   // depth cols

    float nd = a.x * a.x + a.y * a.y + a.z * a.z + a.w * a.w;
    float dp = d.x * d.x + d.y * d.y + d.z * d.z + d.w * d.w;

    uint32_t h0, l0, h1, l1;
    split2(a.x, a.y, h0, l0);
    split2(a.z, a.w, h1, l1);
    ((uint2*)(g_Phi + (size_t)row * 128))[lane] = make_uint2(h0, h1);
    ((uint2*)(g_Plo + (size_t)row * 128))[lane] = make_uint2(l0, l1);

#pragma unroll
    for (int off = 16; off > 0; off >>= 1) {
        nd += __shfl_xor_sync(0xffffffffu, nd, off);
        dp += __shfl_xor_sync(0xffffffffu, dp, off);
    }
    if (lane == 0) {
        g_nd[row] = nd;
        out_depths[row] = dp;
    }
}

// ---------------------------------------------------------------------------
// GEMM2: per-batch Gram G = Pd @ Pd^T (K=128), fused distance epilogue.
// BM=128, BN=64, 2 K-chunks of 64.  grid = (8 ntiles, 4 mtiles, 8 batches).
// ---------------------------------------------------------------------------
__global__ __launch_bounds__(256, 1) void gemm2_wmma(float* __restrict__ out) {
    extern __shared__ __align__(16) char sm[];
    __nv_bfloat16* Ahi = (__nv_bfloat16*)sm;
    __nv_bfloat16* Alo = Ahi + 128 * AP;
    __nv_bfloat16* Bhi = Alo + 128 * AP;
    __nv_bfloat16* Blo = Bhi + 64 * AP;
    float* Csm = (float*)sm;                        // reused: [128][68]

    __shared__ float ndi_s[128];
    __shared__ float ndj_s[64];

    const int tid = threadIdx.x;
    const int wid = tid >> 5;
    const int wm = wid >> 1, wn = wid & 1;
    const int b = blockIdx.z;
    const int m0 = blockIdx.y * 128;
    const int n0 = blockIdx.x * 64;

    const __nv_bfloat16* __restrict__ Ph = g_Phi + (size_t)b * Sn * 128;
    const __nv_bfloat16* __restrict__ Pl = g_Plo + (size_t)b * Sn * 128;
    const float* __restrict__ ndb = g_nd + (size_t)b * Sn;

    if (tid < 128) ndi_s[tid] = ndb[m0 + tid];
    else if (tid < 192) ndj_s[tid - 128] = ndb[n0 + (tid - 128)];

    FragC acc[2][2];
#pragma unroll
    for (int i = 0; i < 2; i++)
#pragma unroll
        for (int j = 0; j < 2; j++) wmma::fill_fragment(acc[i][j], 0.0f);

    const int arow = tid >> 1, acol = (tid & 1) * 32;
    const int brow = tid >> 2, bcol = (tid & 3) * 16;

    for (int c = 0; c < 2; c++) {
        const int k0 = c * 64;
        // A: 128 rows x 64 cols of hi and lo (int4 = 8 bf16)
#pragma unroll
        for (int q = 0; q < 4; q++) {
            int4 vh = *(const int4*)(Ph + (size_t)(m0 + arow) * 128 + k0 + acol + q * 8);
            int4 vl = *(const int4*)(Pl + (size_t)(m0 + arow) * 128 + k0 + acol + q * 8);
            *(int4*)(Ahi + arow * AP + acol + q * 8) = vh;
            *(int4*)(Alo + arow * AP + acol + q * 8) = vl;
        }
#pragma unroll
        for (int q = 0; q < 2; q++) {
            int4 vh = *(const int4*)(Ph + (size_t)(n0 + brow) * 128 + k0 + bcol + q * 8);
            int4 vl = *(const int4*)(Pl + (size_t)(n0 + brow) * 128 + k0 + bcol + q * 8);
            *(int4*)(Bhi + brow * AP + bcol + q * 8) = vh;
            *(int4*)(Blo + brow * AP + bcol + q * 8) = vl;
        }
        __syncthreads();

#pragma unroll
        for (int kk = 0; kk < 64; kk += 16) {
            FragA ah[2], al[2];
            FragB bh[2], bl[2];
#pragma unroll
            for (int f = 0; f < 2; f++) {
                const int r = wm * 32 + f * 16;
                wmma::load_matrix_sync(ah[f], Ahi + r * AP + kk, AP);
                wmma::load_matrix_sync(al[f], Alo + r * AP + kk, AP);
                const int n = wn * 32 + f * 16;
                wmma::load_matrix_sync(bh[f], Bhi + n * AP + kk, AP);
                wmma::load_matrix_sync(bl[f], Blo + n * AP + kk, AP);
            }
#pragma unroll
            for (int i = 0; i < 2; i++)
#pragma unroll
                for (int j = 0; j < 2; j++) {
                    wmma::mma_sync(acc[i][j], ah[i], bh[j], acc[i][j]);
                    wmma::mma_sync(acc[i][j], ah[i], bl[j], acc[i][j]);
                    wmma::mma_sync(acc[i][j], al[i], bh[j], acc[i][j]);
                }
        }
        __syncthreads();
    }

    // Stage accumulators through smem (known element mapping), then fused epilogue
#pragma unroll
    for (int i = 0; i < 2; i++)
#pragma unroll
        for (int j = 0; j < 2; j++)
            wmma::store_matrix_sync(Csm + (wm * 32 + i * 16) * 68 + wn * 32 + j * 16,
                                    acc[i][j], 68, wmma::mem_row_major);
    __syncthreads();

#pragma unroll
    for (int it = 0; it < 2; it++) {
        const int idx = tid + it * 256;      // 0..511
        const int i = idx >> 2;              // row 0..127
        const int q = idx & 3;               // 16-col quad
        const float ndi = ndi_s[i];
        const float* crow = Csm + i * 68 + q * 16;
        float* orow = out + ((size_t)(b * Sn + m0 + i)) * Sn + n0 + q * 16;
#pragma unroll
        for (int j = 0; j < 4; j++) {
            float4 cv = ((const float4*)crow)[j];
            float4 v;
            v.x = ndi + ndj_s[q * 16 + 4 * j + 0] - 2.0f * cv.x;
            v.y = ndi + ndj_s[q * 16 + 4 * j + 1] - 2.0f * cv.y;
            v.z = ndi + ndj_s[q * 16 + 4 * j + 2] - 2.0f * cv.z;
            v.w = ndi + ndj_s[q * 16 + 4 * j + 3] - 2.0f * cv.w;
            ((float4*)orow)[j] = v;
        }
    }
}

// ---------------------------------------------------------------------------
extern "C" void kernel_launch(void* const* d_in, const int* in_sizes, int n_in,
                              void* d_out, int out_size) {
    const float* E  = (const float*)d_in[0];
    const float* Wd = (const float*)d_in[1];
    const float* Wz = (const float*)d_in[2];
    float* out = (float*)d_out;

    cudaFuncSetAttribute(gemm1_wmma, cudaFuncAttributeMaxDynamicSharedMemorySize, SMEM_G);
    cudaFuncSetAttribute(gemm2_wmma, cudaFuncAttributeMaxDynamicSharedMemorySize, SMEM_G);

    gemm1_wmma<<<dim3(4, Mtot / 128), 256, SMEM_G>>>(E, Wd, Wz);
    norms_kernel<<<Mtot / 8, 256>>>(out + (size_t)Bn * Sn * Sn);
    gemm2_wmma<<<dim3(Sn / 64, Sn / 128, Bn), 256, SMEM_G>>>(out);
}

// round 9
// speedup vs baseline: 1.9839x; 1.2180x over previous
#include <cuda_runtime.h>
#include <cuda_bf16.h>
#include <mma.h>
#include <cstdint>

using namespace nvcuda;

// B=8, S=512, D=768, R=128
//   P = E @ [Wd;Wz]^T ; distances[b,i,j] = nd_i + nd_j - 2<Pd_i,Pd_j>; depths = ||Pz||^2
// WMMA bf16 m16n16k16 (plain sm_103 target: no tcgen05), 3-term hi/lo split.
// Pipeline: split(E,W -> bf16 hi/lo gmem) -> gemm1 (P + norms + Phi/Plo, fused) -> gemm2.

static constexpr int Bn = 8;
static constexpr int Sn = 512;
static constexpr int Dn = 768;
static constexpr int Mtot = Bn * Sn;      // 4096

// Scratch
__device__ __align__(256) __nv_bfloat16 g_Ehi[Mtot * Dn];
__device__ __align__(256) __nv_bfloat16 g_Elo[Mtot * Dn];
__device__ __align__(256) __nv_bfloat16 g_Whi[256 * Dn];   // rows 0-127 Wd, 128-255 Wz
__device__ __align__(256) __nv_bfloat16 g_Wlo[256 * Dn];
__device__ __align__(256) __nv_bfloat16 g_Phi[Mtot * 128]; // dist projection hi
__device__ __align__(256) __nv_bfloat16 g_Plo[Mtot * 128]; // dist projection lo
__device__ float g_nd[Mtot];

__device__ __forceinline__ uint32_t smem_u32(const void* p) {
    return (uint32_t)__cvta_generic_to_shared(p);
}
__device__ __forceinline__ void cp16(uint32_t dst, const void* src) {
    asm volatile("cp.async.cg.shared.global [%0], [%1], 16;"
                 :: "r"(dst), "l"(__cvta_generic_to_global(src)) : "memory");
}
__device__ __forceinline__ void cp_commit() {
    asm volatile("cp.async.commit_group;" ::: "memory");
}
template <int N> __device__ __forceinline__ void cp_wait() {
    asm volatile("cp.async.wait_group %0;" :: "n"(N) : "memory");
}
// split fp32 pair -> packed bf16 hi pair + packed bf16 lo (residual) pair
__device__ __forceinline__ void split2(float a, float b, uint32_t& h2, uint32_t& l2) {
    __nv_bfloat16 ha = __float2bfloat16(a), hb = __float2bfloat16(b);
    float ra = a - __bfloat162float(ha);
    float rb = b - __bfloat162float(hb);
    __nv_bfloat16 la = __float2bfloat16(ra), lb = __float2bfloat16(rb);
    h2 = (uint32_t)__bfloat16_as_ushort(ha) | ((uint32_t)__bfloat16_as_ushort(hb) << 16);
    l2 = (uint32_t)__bfloat16_as_ushort(la) | ((uint32_t)__bfloat16_as_ushort(lb) << 16);
}

typedef wmma::fragment<wmma::matrix_a, 16, 16, 16, __nv_bfloat16, wmma::row_major> FragA;
typedef wmma::fragment<wmma::matrix_b, 16, 16, 16, __nv_bfloat16, wmma::col_major> FragB;
typedef wmma::fragment<wmma::accumulator, 16, 16, 16, float> FragC;

// ---------------------------------------------------------------------------
// Prepass: split E, Wd, Wz (fp32) into bf16 hi/lo in gmem. 1 float4 / thread.
// E: 786432 float4;  W (Wd then Wz): 49152 float4 (uint2 index == float4 index).
// ---------------------------------------------------------------------------
static constexpr int E4 = (Mtot * Dn) / 4;        // 786432
static constexpr int W4 = (128 * Dn) / 4;         // 24576 per matrix
static constexpr int TOT4 = E4 + 2 * W4;          // 835584

__global__ __launch_bounds__(256) void split_kernel(const float4* __restrict__ Ein,
                                                    const float4* __restrict__ Wd,
                                                    const float4* __restrict__ Wz) {
    const int idx = blockIdx.x * 256 + threadIdx.x;
    if (idx >= TOT4) return;
    float4 v;
    uint2 *dhi, *dlo;
    if (idx < E4) {
        v = Ein[idx];
        dhi = (uint2*)g_Ehi + idx;
        dlo = (uint2*)g_Elo + idx;
    } else {
        const int w = idx - E4;
        v = (w < W4) ? Wd[w] : Wz[w - W4];
        dhi = (uint2*)g_Whi + w;
        dlo = (uint2*)g_Wlo + w;
    }
    uint32_t h0, l0, h1, l1;
    split2(v.x, v.y, h0, l0);
    split2(v.z, v.w, h1, l1);
    *dhi = make_uint2(h0, h1);
    *dlo = make_uint2(l0, l1);
}

// ---------------------------------------------------------------------------
// GEMM1: BM=32, BN=128, BK=64, 128 threads (4 warps, warp tile 32x32).
// grid = (2 ntiles [dist|depth], 128 mtiles). cp.async double-buffered.
// Epilogue (full 128 cols in-CTA): row norms + Phi/Plo split, no fp32 P.
// ---------------------------------------------------------------------------
static constexpr int P1 = 72;                        // padded lda (bf16)
static constexpr int A1SZ = 32 * P1;                 // one A tile (elems)
static constexpr int B1SZ = 128 * P1;                // one B tile
static constexpr int BUF1 = 2 * A1SZ + 2 * B1SZ;     // Ahi Alo Bhi Blo = 23040 elems
static constexpr int SMEM1 = 2 * BUF1 * 2;           // 92160 bytes

__global__ __launch_bounds__(128, 2) void gemm1_k(float* __restrict__ depths_out) {
    extern __shared__ __align__(16) char sm[];
    __nv_bfloat16* base = (__nv_bfloat16*)sm;

    const int tid = threadIdx.x;
    const int wid = tid >> 5;
    const int nt = blockIdx.x;           // 0: dist, 1: depth
    const int m0 = blockIdx.y * 32;
    const int nrow0 = nt * 128;

    const int qrow = tid >> 3, qc8 = (tid & 7) * 8;  // cp.async tiling (16 rows/pass)

    // Prologue + per-chunk loader
    auto load_chunk = [&](int c, int buf) {
        const int k0 = c * 64;
        __nv_bfloat16* Ah = base + buf * BUF1;
        __nv_bfloat16* Al = Ah + A1SZ;
        __nv_bfloat16* Bh = Al + A1SZ;
        __nv_bfloat16* Bl = Bh + B1SZ;
        const uint32_t sAh = smem_u32(Ah), sAl = smem_u32(Al);
        const uint32_t sBh = smem_u32(Bh), sBl = smem_u32(Bl);
#pragma unroll
        for (int i = 0; i < 2; i++) {                // A: 32 rows x 64 cols
            const int r = qrow + i * 16;
            const uint32_t d = (uint32_t)(r * P1 + qc8) * 2;
            const size_t s = (size_t)(m0 + r) * Dn + k0 + qc8;
            cp16(sAh + d, g_Ehi + s);
            cp16(sAl + d, g_Elo + s);
        }
#pragma unroll
        for (int i = 0; i < 8; i++) {                // B: 128 rows x 64 cols
            const int r = qrow + i * 16;
            const uint32_t d = (uint32_t)(r * P1 + qc8) * 2;
            const size_t s = (size_t)(nrow0 + r) * Dn + k0 + qc8;
            cp16(sBh + d, g_Whi + s);
            cp16(sBl + d, g_Wlo + s);
        }
        cp_commit();
    };

    FragC acc[2][2];
#pragma unroll
    for (int i = 0; i < 2; i++)
#pragma unroll
        for (int j = 0; j < 2; j++) wmma::fill_fragment(acc[i][j], 0.0f);

    load_chunk(0, 0);
    for (int c = 0; c < 12; c++) {
        if (c < 11) load_chunk(c + 1, (c + 1) & 1);
        if (c < 11) cp_wait<1>(); else cp_wait<0>();
        __syncthreads();

        const __nv_bfloat16* Ah = base + (c & 1) * BUF1;
        const __nv_bfloat16* Al = Ah + A1SZ;
        const __nv_bfloat16* Bh = Al + A1SZ;
        const __nv_bfloat16* Bl = Bh + B1SZ;
#pragma unroll
        for (int kk = 0; kk < 64; kk += 16) {
            FragA ah[2], al[2];
            FragB bh[2], bl[2];
#pragma unroll
            for (int f = 0; f < 2; f++) {
                wmma::load_matrix_sync(ah[f], Ah + (f * 16) * P1 + kk, P1);
                wmma::load_matrix_sync(al[f], Al + (f * 16) * P1 + kk, P1);
                const int n = wid * 32 + f * 16;
                wmma::load_matrix_sync(bh[f], Bh + n * P1 + kk, P1);
                wmma::load_matrix_sync(bl[f], Bl + n * P1 + kk, P1);
            }
#pragma unroll
            for (int i = 0; i < 2; i++)
#pragma unroll
                for (int j = 0; j < 2; j++) {
                    wmma::mma_sync(acc[i][j], ah[i], bh[j], acc[i][j]);
                    wmma::mma_sync(acc[i][j], ah[i], bl[j], acc[i][j]);
                    wmma::mma_sync(acc[i][j], al[i], bh[j], acc[i][j]);
                }
        }
        __syncthreads();
    }

    // Epilogue: stage fp32 tile, then norms + split (dist) / depths (depth)
    float* Csm = (float*)sm;                         // [32][136]
#pragma unroll
    for (int i = 0; i < 2; i++)
#pragma unroll
        for (int j = 0; j < 2; j++)
            wmma::store_matrix_sync(Csm + (i * 16) * 136 + wid * 32 + j * 16,
                                    acc[i][j], 136, wmma::mem_row_major);
    __syncthreads();

    const int row = tid >> 2;            // 0..31
    const int part = tid & 3;            // 32-col quarter
    const float* cr = Csm + row * 136 + part * 32;
    float4 vv[8];
    float norm = 0.0f;
#pragma unroll
    for (int q = 0; q < 8; q++) {
        vv[q] = ((const float4*)cr)[q];
        norm += vv[q].x * vv[q].x + vv[q].y * vv[q].y +
                vv[q].z * vv[q].z + vv[q].w * vv[q].w;
    }
    norm += __shfl_xor_sync(0xffffffffu, norm, 1);
    norm += __shfl_xor_sync(0xffffffffu, norm, 2);

    const int grow = m0 + row;
    if (nt == 0) {
        uint2* dh = (uint2*)(g_Phi + (size_t)grow * 128 + part * 32);
        uint2* dl = (uint2*)(g_Plo + (size_t)grow * 128 + part * 32);
#pragma unroll
        for (int q = 0; q < 8; q++) {
            uint32_t h0, l0, h1, l1;
            split2(vv[q].x, vv[q].y, h0, l0);
            split2(vv[q].z, vv[q].w, h1, l1);
            dh[q] = make_uint2(h0, h1);
            dl[q] = make_uint2(l0, l1);
        }
        if (part == 0) g_nd[grow] = norm;
    } else {
        if (part == 0) depths_out[grow] = norm;
    }
}

// ---------------------------------------------------------------------------
// GEMM2: per-batch Gram + distance epilogue. BM=64, BN=128, K=128 (one shot).
// 256 threads (8 warps, 2x4, warp tile 32x32). grid = (4, 8, 8) = 256 CTAs.
// ---------------------------------------------------------------------------
static constexpr int P2 = 136;                       // padded lda (bf16)
static constexpr int A2SZ = 64 * P2;
static constexpr int B2SZ = 128 * P2;
static constexpr int SMEM2 = (2 * A2SZ + 2 * B2SZ) * 2;   // 104448 bytes

__global__ __launch_bounds__(256, 2) void gemm2_k(float* __restrict__ out) {
    extern __shared__ __align__(16) char sm[];
    __nv_bfloat16* Ah = (__nv_bfloat16*)sm;
    __nv_bfloat16* Al = Ah + A2SZ;
    __nv_bfloat16* Bh = Al + A2SZ;
    __nv_bfloat16* Bl = Bh + B2SZ;
    __shared__ float ndi_s[64];
    __shared__ float ndj_s[128];

    const int tid = threadIdx.x;
    const int wid = tid >> 5;
    const int wm = wid >> 2, wn = wid & 3;
    const int b = blockIdx.z;
    const int m0 = blockIdx.y * 64;
    const int n0 = blockIdx.x * 128;
    const size_t pbase = (size_t)b * Sn * 128;

    const float* __restrict__ ndb = g_nd + (size_t)b * Sn;
    if (tid < 64) ndi_s[tid] = ndb[m0 + tid];
    else if (tid < 192) ndj_s[tid - 64] = ndb[n0 + tid - 64];

    // One-shot cp.async of full K=128 tiles
    {
        const int r16 = tid >> 4, c16 = (tid & 15) * 8;   // 16 rows/pass, 16 chunks/row
        const uint32_t sAh = smem_u32(Ah), sAl = smem_u32(Al);
        const uint32_t sBh = smem_u32(Bh), sBl = smem_u32(Bl);
#pragma unroll
        for (int i = 0; i < 4; i++) {                     // A: 64 rows
            const int r = r16 + i * 16;
            const uint32_t d = (uint32_t)(r * P2 + c16) * 2;
            const size_t s = pbase + (size_t)(m0 + r) * 128 + c16;
            cp16(sAh + d, g_Phi + s);
            cp16(sAl + d, g_Plo + s);
        }
#pragma unroll
        for (int i = 0; i < 8; i++) {                     // B: 128 rows
            const int r = r16 + i * 16;
            const uint32_t d = (uint32_t)(r * P2 + c16) * 2;
            const size_t s = pbase + (size_t)(n0 + r) * 128 + c16;
            cp16(sBh + d, g_Phi + s);
            cp16(sBl + d, g_Plo + s);
        }
        cp_commit();
        cp_wait<0>();
    }
    __syncthreads();

    FragC acc[2][2];
#pragma unroll
    for (int i = 0; i < 2; i++)
#pragma unroll
        for (int j = 0; j < 2; j++) wmma::fill_fragment(acc[i][j], 0.0f);

#pragma unroll
    for (int kk = 0; kk < 128; kk += 16) {
        FragA ah[2], al[2];
        FragB bh[2], bl[2];
#pragma unroll
        for (int f = 0; f < 2; f++) {
            const int r = wm * 32 + f * 16;
            wmma::load_matrix_sync(ah[f], Ah + r * P2 + kk, P2);
            wmma::load_matrix_sync(al[f], Al + r * P2 + kk, P2);
            const int n = wn * 32 + f * 16;
            wmma::load_matrix_sync(bh[f], Bh + n * P2 + kk, P2);
            wmma::load_matrix_sync(bl[f], Bl + n * P2 + kk, P2);
        }
#pragma unroll
        for (int i = 0; i < 2; i++)
#pragma unroll
            for (int j = 0; j < 2; j++) {
                wmma::mma_sync(acc[i][j], ah[i], bh[j], acc[i][j]);
                wmma::mma_sync(acc[i][j], ah[i], bl[j], acc[i][j]);
                wmma::mma_sync(acc[i][j], al[i], bh[j], acc[i][j]);
            }
    }
    __syncthreads();

    // Stage fp32 Gram, fused distance epilogue
    float* Csm = (float*)sm;                              // [64][136]
#pragma unroll
    for (int i = 0; i < 2; i++)
#pragma unroll
        for (int j = 0; j < 2; j++)
            wmma::store_matrix_sync(Csm + (wm * 32 + i * 16) * 136 + wn * 32 + j * 16,
                                    acc[i][j], 136, wmma::mem_row_major);
    __syncthreads();

    const int row = tid >> 2;            // 0..63
    const int part = tid & 3;            // 32-col quarter of 128
    const float ndi = ndi_s[row];
    const float* cr = Csm + row * 136 + part * 32;
    const float* nj = ndj_s + part * 32;
    float* orow = out + ((size_t)(b * Sn + m0 + row)) * Sn + n0 + part * 32;
#pragma unroll
    for (int q = 0; q < 8; q++) {
        float4 cv = ((const float4*)cr)[q];
        float4 v;
        v.x = ndi + nj[4 * q + 0] - 2.0f * cv.x;
        v.y = ndi + nj[4 * q + 1] - 2.0f * cv.y;
        v.z = ndi + nj[4 * q + 2] - 2.0f * cv.z;
        v.w = ndi + nj[4 * q + 3] - 2.0f * cv.w;
        ((float4*)orow)[q] = v;
    }
}

// ---------------------------------------------------------------------------
extern "C" void kernel_launch(void* const* d_in, const int* in_sizes, int n_in,
                              void* d_out, int out_size) {
    const float4* E  = (const float4*)d_in[0];
    const float4* Wd = (const float4*)d_in[1];
    const float4* Wz = (const float4*)d_in[2];
    float* out = (float*)d_out;

    cudaFuncSetAttribute(gemm1_k, cudaFuncAttributeMaxDynamicSharedMemorySize, SMEM1);
    cudaFuncSetAttribute(gemm2_k, cudaFuncAttributeMaxDynamicSharedMemorySize, SMEM2);

    split_kernel<<<(TOT4 + 255) / 256, 256>>>(E, Wd, Wz);
    gemm1_k<<<dim3(2, Mtot / 32), 128, SMEM1>>>(out + (size_t)Bn * Sn * Sn);
    gemm2_k<<<dim3(Sn / 128, Sn / 64, Bn), 256, SMEM2>>>(out);
}

// round 10
// speedup vs baseline: 2.0875x; 1.0522x over previous
#include <cuda_runtime.h>
#include <cuda_bf16.h>
#include <mma.h>
#include <cstdint>

using namespace nvcuda;

// B=8, S=512, D=768, R=128
//   P = E @ [Wd;Wz]^T ; distances[b,i,j] = nd_i + nd_j - 2<Pd_i,Pd_j>; depths = ||Pz||^2
// WMMA bf16 m16n16k16 (plain sm_103 target: no tcgen05).
// gemm1: 3-term hi/lo split (~fp32).  gemm2: 2-term (err ~1e-4 << 1e-3 threshold).

static constexpr int Bn = 8;
static constexpr int Sn = 512;
static constexpr int Dn = 768;
static constexpr int Mtot = Bn * Sn;      // 4096

// Scratch
__device__ __align__(256) __nv_bfloat16 g_Ehi[Mtot * Dn];
__device__ __align__(256) __nv_bfloat16 g_Elo[Mtot * Dn];
__device__ __align__(256) __nv_bfloat16 g_Whi[256 * Dn];   // rows 0-127 Wd, 128-255 Wz
__device__ __align__(256) __nv_bfloat16 g_Wlo[256 * Dn];
__device__ __align__(256) __nv_bfloat16 g_Phi[Mtot * 128]; // dist projection hi
__device__ __align__(256) __nv_bfloat16 g_Plo[Mtot * 128]; // dist projection lo
__device__ float g_nd[Mtot];

__device__ __forceinline__ uint32_t smem_u32(const void* p) {
    return (uint32_t)__cvta_generic_to_shared(p);
}
__device__ __forceinline__ void cp16(uint32_t dst, const void* src) {
    asm volatile("cp.async.cg.shared.global [%0], [%1], 16;"
                 :: "r"(dst), "l"(__cvta_generic_to_global(src)) : "memory");
}
__device__ __forceinline__ void cp_commit() {
    asm volatile("cp.async.commit_group;" ::: "memory");
}
template <int N> __device__ __forceinline__ void cp_wait() {
    asm volatile("cp.async.wait_group %0;" :: "n"(N) : "memory");
}
__device__ __forceinline__ void split2(float a, float b, uint32_t& h2, uint32_t& l2) {
    __nv_bfloat16 ha = __float2bfloat16(a), hb = __float2bfloat16(b);
    float ra = a - __bfloat162float(ha);
    float rb = b - __bfloat162float(hb);
    __nv_bfloat16 la = __float2bfloat16(ra), lb = __float2bfloat16(rb);
    h2 = (uint32_t)__bfloat16_as_ushort(ha) | ((uint32_t)__bfloat16_as_ushort(hb) << 16);
    l2 = (uint32_t)__bfloat16_as_ushort(la) | ((uint32_t)__bfloat16_as_ushort(lb) << 16);
}

typedef wmma::fragment<wmma::matrix_a, 16, 16, 16, __nv_bfloat16, wmma::row_major> FragA;
typedef wmma::fragment<wmma::matrix_b, 16, 16, 16, __nv_bfloat16, wmma::col_major> FragB;
typedef wmma::fragment<wmma::accumulator, 16, 16, 16, float> FragC;

// ---------------------------------------------------------------------------
// Prepass: split fp32 -> bf16 hi/lo, 2 float4 in -> 1 uint4 out per array.
// ---------------------------------------------------------------------------
static constexpr int E4 = (Mtot * Dn) / 4;    // 786432 float4 in E
static constexpr int E8 = E4 / 2;             // 393216 threads for E
static constexpr int W4 = (128 * Dn) / 4;     // 24576 float4 per W matrix
static constexpr int W8 = W4;                 // 24576 threads for both W (2 f4 each)
static constexpr int TOT8 = E8 + W8;          // 417792 = 1632 * 256

__global__ __launch_bounds__(256) void split_kernel(const float4* __restrict__ Ein,
                                                    const float4* __restrict__ Wd,
                                                    const float4* __restrict__ Wz) {
    const int idx = blockIdx.x * 256 + threadIdx.x;
    if (idx >= TOT8) return;
    float4 v0, v1;
    uint4 *dhi, *dlo;
    if (idx < E8) {
        v0 = Ein[2 * idx];
        v1 = Ein[2 * idx + 1];
        dhi = (uint4*)g_Ehi + idx;
        dlo = (uint4*)g_Elo + idx;
    } else {
        const int w = idx - E8;          // 0..24575, pair index into [Wd|Wz]
        const int f = 2 * w;
        if (f < W4) { v0 = Wd[f]; v1 = Wd[f + 1]; }
        else        { v0 = Wz[f - W4]; v1 = Wz[f - W4 + 1]; }
        dhi = (uint4*)g_Whi + w;
        dlo = (uint4*)g_Wlo + w;
    }
    uint4 h, l;
    split2(v0.x, v0.y, h.x, l.x);
    split2(v0.z, v0.w, h.y, l.y);
    split2(v1.x, v1.y, h.z, l.z);
    split2(v1.z, v1.w, h.w, l.w);
    *dhi = h;
    *dlo = l;
}

// ---------------------------------------------------------------------------
// GEMM1: BM=64, BN=128, BK=64, 256 threads (8 warps 2x4, warp tile 32x32).
// 3-term. grid = (2 ntiles [dist|depth], 64 mtiles) = 128 CTAs, double-buffered.
// Epilogue: row norms + Phi/Plo split (dist) / depths (depth) inline.
// ---------------------------------------------------------------------------
static constexpr int P1 = 72;
static constexpr int A1SZ = 64 * P1;
static constexpr int B1SZ = 128 * P1;
static constexpr int BUF1 = 2 * A1SZ + 2 * B1SZ;     // 27648 elems
static constexpr int SMEM1 = 2 * BUF1 * 2;           // 110592 B

__global__ __launch_bounds__(256, 1) void gemm1_k(float* __restrict__ depths_out) {
    extern __shared__ __align__(16) char sm[];
    __nv_bfloat16* base = (__nv_bfloat16*)sm;

    const int tid = threadIdx.x;
    const int wid = tid >> 5;
    const int wm = wid >> 2, wn = wid & 3;
    const int nt = blockIdx.x;           // 0: dist, 1: depth
    const int m0 = blockIdx.y * 64;
    const int nrow0 = nt * 128;

    const int qrow = tid >> 3, qc8 = (tid & 7) * 8;  // 32 rows per pass

    auto load_chunk = [&](int c, int buf) {
        const int k0 = c * 64;
        __nv_bfloat16* Ah = base + buf * BUF1;
        __nv_bfloat16* Al = Ah + A1SZ;
        __nv_bfloat16* Bh = Al + A1SZ;
        __nv_bfloat16* Bl = Bh + B1SZ;
        const uint32_t sAh = smem_u32(Ah), sAl = smem_u32(Al);
        const uint32_t sBh = smem_u32(Bh), sBl = smem_u32(Bl);
#pragma unroll
        for (int i = 0; i < 2; i++) {                // A: 64 rows x 64 cols
            const int r = qrow + i * 32;
            const uint32_t d = (uint32_t)(r * P1 + qc8) * 2;
            const size_t s = (size_t)(m0 + r) * Dn + k0 + qc8;
            cp16(sAh + d, g_Ehi + s);
            cp16(sAl + d, g_Elo + s);
        }
#pragma unroll
        for (int i = 0; i < 4; i++) {                // B: 128 rows x 64 cols
            const int r = qrow + i * 32;
            const uint32_t d = (uint32_t)(r * P1 + qc8) * 2;
            const size_t s = (size_t)(nrow0 + r) * Dn + k0 + qc8;
            cp16(sBh + d, g_Whi + s);
            cp16(sBl + d, g_Wlo + s);
        }
        cp_commit();
    };

    FragC acc[2][2];
#pragma unroll
    for (int i = 0; i < 2; i++)
#pragma unroll
        for (int j = 0; j < 2; j++) wmma::fill_fragment(acc[i][j], 0.0f);

    load_chunk(0, 0);
    for (int c = 0; c < 12; c++) {
        if (c < 11) { load_chunk(c + 1, (c + 1) & 1); cp_wait<1>(); }
        else cp_wait<0>();
        __syncthreads();

        const __nv_bfloat16* Ah = base + (c & 1) * BUF1;
        const __nv_bfloat16* Al = Ah + A1SZ;
        const __nv_bfloat16* Bh = Al + A1SZ;
        const __nv_bfloat16* Bl = Bh + B1SZ;
#pragma unroll
        for (int kk = 0; kk < 64; kk += 16) {
            FragA ah[2], al[2];
            FragB bh[2], bl[2];
#pragma unroll
            for (int f = 0; f < 2; f++) {
                const int r = wm * 32 + f * 16;
                wmma::load_matrix_sync(ah[f], Ah + r * P1 + kk, P1);
                wmma::load_matrix_sync(al[f], Al + r * P1 + kk, P1);
                const int n = wn * 32 + f * 16;
                wmma::load_matrix_sync(bh[f], Bh + n * P1 + kk, P1);
                wmma::load_matrix_sync(bl[f], Bl + n * P1 + kk, P1);
            }
#pragma unroll
            for (int i = 0; i < 2; i++)
#pragma unroll
                for (int j = 0; j < 2; j++) {
                    wmma::mma_sync(acc[i][j], ah[i], bh[j], acc[i][j]);
                    wmma::mma_sync(acc[i][j], ah[i], bl[j], acc[i][j]);
                    wmma::mma_sync(acc[i][j], al[i], bh[j], acc[i][j]);
                }
        }
        __syncthreads();
    }

    // Epilogue: stage fp32 tile, norms + split (dist) / depths (depth)
    float* Csm = (float*)sm;                         // [64][136]
#pragma unroll
    for (int i = 0; i < 2; i++)
#pragma unroll
        for (int j = 0; j < 2; j++)
            wmma::store_matrix_sync(Csm + (wm * 32 + i * 16) * 136 + wn * 32 + j * 16,
                                    acc[i][j], 136, wmma::mem_row_major);
    __syncthreads();

    const int row = tid >> 2;            // 0..63
    const int part = tid & 3;            // 32-col quarter
    const float* cr = Csm + row * 136 + part * 32;
    float4 vv[8];
    float norm = 0.0f;
#pragma unroll
    for (int q = 0; q < 8; q++) {
        vv[q] = ((const float4*)cr)[q];
        norm += vv[q].x * vv[q].x + vv[q].y * vv[q].y +
                vv[q].z * vv[q].z + vv[q].w * vv[q].w;
    }
    norm += __shfl_xor_sync(0xffffffffu, norm, 1);
    norm += __shfl_xor_sync(0xffffffffu, norm, 2);

    const int grow = m0 + row;
    if (nt == 0) {
        uint2* dh = (uint2*)(g_Phi + (size_t)grow * 128 + part * 32);
        uint2* dl = (uint2*)(g_Plo + (size_t)grow * 128 + part * 32);
#pragma unroll
        for (int q = 0; q < 8; q++) {
            uint32_t h0, l0, h1, l1;
            split2(vv[q].x, vv[q].y, h0, l0);
            split2(vv[q].z, vv[q].w, h1, l1);
            dh[q] = make_uint2(h0, h1);
            dl[q] = make_uint2(l0, l1);
        }
        if (part == 0) g_nd[grow] = norm;
    } else {
        if (part == 0) depths_out[grow] = norm;
    }
}

// ---------------------------------------------------------------------------
// GEMM2: per-batch Gram (2-term: Ph.Ph^T + Ph.Plo^T) + distance epilogue.
// BM=64, BN=128, BK=64 x2 double-buffered. 256 thr (8 warps 2x4, warp 32x32).
// grid = (4, 8, 8) = 256 CTAs, occupancy 2.
// ---------------------------------------------------------------------------
static constexpr int P2 = 72;
static constexpr int A2SZ = 64 * P2;                 // A hi only
static constexpr int B2SZ = 128 * P2;
static constexpr int BUF2 = A2SZ + 2 * B2SZ;         // 23040 elems
static constexpr int SMEM2 = 2 * BUF2 * 2;           // 92160 B

__global__ __launch_bounds__(256, 2) void gemm2_k(float* __restrict__ out) {
    extern __shared__ __align__(16) char sm[];
    __nv_bfloat16* base = (__nv_bfloat16*)sm;
    __shared__ float ndi_s[64];
    __shared__ float ndj_s[128];

    const int tid = threadIdx.x;
    const int wid = tid >> 5;
    const int wm = wid >> 2, wn = wid & 3;
    const int b = blockIdx.z;
    const int m0 = blockIdx.y * 64;
    const int n0 = blockIdx.x * 128;
    const size_t pbase = (size_t)b * Sn * 128;

    const float* __restrict__ ndb = g_nd + (size_t)b * Sn;
    if (tid < 64) ndi_s[tid] = ndb[m0 + tid];
    else if (tid < 192) ndj_s[tid - 64] = ndb[n0 + tid - 64];

    const int qrow = tid >> 3, qc8 = (tid & 7) * 8;

    auto load_chunk = [&](int c, int buf) {
        const int k0 = c * 64;
        __nv_bfloat16* Ah = base + buf * BUF2;
        __nv_bfloat16* Bh = Ah + A2SZ;
        __nv_bfloat16* Bl = Bh + B2SZ;
        const uint32_t sAh = smem_u32(Ah), sBh = smem_u32(Bh), sBl = smem_u32(Bl);
#pragma unroll
        for (int i = 0; i < 2; i++) {                // A: 64 rows (hi only)
            const int r = qrow + i * 32;
            const uint32_t d = (uint32_t)(r * P2 + qc8) * 2;
            cp16(sAh + d, g_Phi + pbase + (size_t)(m0 + r) * 128 + k0 + qc8);
        }
#pragma unroll
        for (int i = 0; i < 4; i++) {                // B: 128 rows hi+lo
            const int r = qrow + i * 32;
            const uint32_t d = (uint32_t)(r * P2 + qc8) * 2;
            const size_t s = pbase + (size_t)(n0 + r) * 128 + k0 + qc8;
            cp16(sBh + d, g_Phi + s);
            cp16(sBl + d, g_Plo + s);
        }
        cp_commit();
    };

    FragC acc[2][2];
#pragma unroll
    for (int i = 0; i < 2; i++)
#pragma unroll
        for (int j = 0; j < 2; j++) wmma::fill_fragment(acc[i][j], 0.0f);

    load_chunk(0, 0);
    for (int c = 0; c < 2; c++) {
        if (c < 1) { load_chunk(1, 1); cp_wait<1>(); }
        else cp_wait<0>();
        __syncthreads();

        const __nv_bfloat16* Ah = base + (c & 1) * BUF2;
        const __nv_bfloat16* Bh = Ah + A2SZ;
        const __nv_bfloat16* Bl = Bh + B2SZ;
#pragma unroll
        for (int kk = 0; kk < 64; kk += 16) {
            FragA ah[2];
            FragB bh[2], bl[2];
#pragma unroll
            for (int f = 0; f < 2; f++) {
                wmma::load_matrix_sync(ah[f], Ah + (wm * 32 + f * 16) * P2 + kk, P2);
                const int n = wn * 32 + f * 16;
                wmma::load_matrix_sync(bh[f], Bh + n * P2 + kk, P2);
                wmma::load_matrix_sync(bl[f], Bl + n * P2 + kk, P2);
            }
#pragma unroll
            for (int i = 0; i < 2; i++)
#pragma unroll
                for (int j = 0; j < 2; j++) {
                    wmma::mma_sync(acc[i][j], ah[i], bh[j], acc[i][j]);
                    wmma::mma_sync(acc[i][j], ah[i], bl[j], acc[i][j]);
                }
        }
        __syncthreads();
    }

    // Stage fp32 Gram, fused distance epilogue
    float* Csm = (float*)sm;                              // [64][136]
#pragma unroll
    for (int i = 0; i < 2; i++)
#pragma unroll
        for (int j = 0; j < 2; j++)
            wmma::store_matrix_sync(Csm + (wm * 32 + i * 16) * 136 + wn * 32 + j * 16,
                                    acc[i][j], 136, wmma::mem_row_major);
    __syncthreads();

    const int row = tid >> 2;            // 0..63
    const int part = tid & 3;            // 32-col quarter of 128
    const float ndi = ndi_s[row];
    const float* cr = Csm + row * 136 + part * 32;
    const float* nj = ndj_s + part * 32;
    float* orow = out + ((size_t)(b * Sn + m0 + row)) * Sn + n0 + part * 32;
#pragma unroll
    for (int q = 0; q < 8; q++) {
        float4 cv = ((const float4*)cr)[q];
        float4 v;
        v.x = ndi + nj[4 * q + 0] - 2.0f * cv.x;
        v.y = ndi + nj[4 * q + 1] - 2.0f * cv.y;
        v.z = ndi + nj[4 * q + 2] - 2.0f * cv.z;
        v.w = ndi + nj[4 * q + 3] - 2.0f * cv.w;
        ((float4*)orow)[q] = v;
    }
}

// ---------------------------------------------------------------------------
extern "C" void kernel_launch(void* const* d_in, const int* in_sizes, int n_in,
                              void* d_out, int out_size) {
    const float4* E  = (const float4*)d_in[0];
    const float4* Wd = (const float4*)d_in[1];
    const float4* Wz = (const float4*)d_in[2];
    float* out = (float*)d_out;

    cudaFuncSetAttribute(gemm1_k, cudaFuncAttributeMaxDynamicSharedMemorySize, SMEM1);
    cudaFuncSetAttribute(gemm2_k, cudaFuncAttributeMaxDynamicSharedMemorySize, SMEM2);

    split_kernel<<<TOT8 / 256, 256>>>(E, Wd, Wz);
    gemm1_k<<<dim3(2, Mtot / 64), 256, SMEM1>>>(out + (size_t)Bn * Sn * Sn);
    gemm2_k<<<dim3(Sn / 128, Sn / 64, Bn), 256, SMEM2>>>(out);
}